// round 6
// baseline (speedup 1.0000x reference)
#include <cuda_runtime.h>
#include <cuda_bf16.h>
#include <cstdint>

// out[n, d] = input[n, d] * W[d];  N=16384, D=4096, fp32.
// Pure stream: 256MB read-once + 256MB write-once. DRAM-bound at ~6.4TB/s.
//
// R4 changes vs R3:
//  - CTA owns a fully CONTIGUOUS 64KB region: 512 threads cover half a row
//    (8KB) and iterate 8 row-steps -> long contiguous read bursts then write
//    bursts per CTA (DRAM page locality, fewer rd/wr turnarounds).
//  - R=8 (regs ~40) restores occupancy (R3 was 30%) for more chipwide MLP.
//  - Keep __ldcs/__stcs streaming hints and per-thread W register.

static constexpr int N_ROWS = 16384;
static constexpr int D4 = 4096 / 4;              // 1024 float4 per row
static constexpr int THREADS = 512;
static constexpr int HALF = D4 / THREADS;        // 2 halves per row
static constexpr int R = 8;                      // row-steps per CTA
// Each CTA: fixed half (0/1), rows [g*R, g*R+8). Region is contiguous because
// consecutive "virtual rows" of width 512 float4 tile memory linearly.
static constexpr int GRID = (N_ROWS * HALF) / R; // 4096

__global__ void __launch_bounds__(THREADS) diag_scale_burst_kernel(
    const float4* __restrict__ in,
    const float4* __restrict__ w,
    float4* __restrict__ out)
{
    // Treat memory as rows of 512 float4 (half-rows). Virtual row v maps to
    // real (row = v>>1, half = v&1). CTA b owns virtual rows [b*R, b*R+R),
    // i.e. a contiguous 64KB span starting at b*R*512 float4s.
    unsigned vbase = blockIdx.x * (unsigned)R;          // first virtual row
    unsigned col   = ((vbase & 1u) ? THREADS : 0u) + threadIdx.x; // D4-column of first vrow
    // Since R is even and vbase = b*8 is even, (vbase&1)==0 always:
    col = threadIdx.x + ((vbase & 1u) * THREADS);

    unsigned base = vbase * THREADS + threadIdx.x;      // linear float4 index

    // W for this thread's column; within the 8 virtual rows the real column
    // alternates only if R were odd — here vbase even & each vrow advances
    // the half: vrow v has real col = (v&1)*512 + tid. Rows alternate halves!
    // So precompute both W values.
    float4 w_even = __ldg(&w[threadIdx.x]);             // half 0
    float4 w_odd  = __ldg(&w[THREADS + threadIdx.x]);   // half 1

    float4 a[R];
#pragma unroll
    for (int i = 0; i < R; i++)
        a[i] = __ldcs(&in[base + (unsigned)i * THREADS]);

#pragma unroll
    for (int i = 0; i < R; i++) {
        // virtual row vbase+i: half = (vbase+i)&1 = i&1 (vbase even)
        float4 wv = (i & 1) ? w_odd : w_even;
        float4 r;
        r.x = a[i].x * wv.x;
        r.y = a[i].y * wv.y;
        r.z = a[i].z * wv.z;
        r.w = a[i].w * wv.w;
        __stcs(&out[base + (unsigned)i * THREADS], r);
    }
}

extern "C" void kernel_launch(void* const* d_in, const int* in_sizes, int n_in,
                              void* d_out, int out_size) {
    const float4* in = (const float4*)d_in[0];
    const float4* w  = (const float4*)d_in[1];
    float4* out = (float4*)d_out;
    diag_scale_burst_kernel<<<GRID, THREADS>>>(in, w, out);
}

// round 7
// speedup vs baseline: 1.0023x; 1.0023x over previous
#include <cuda_runtime.h>
#include <cuda_bf16.h>
#include <cstdint>

// out[n, d] = input[n, d] * W[d];  N=16384, D=4096, fp32.
// Pure stream: 256MB read + 256MB write. DRAM-bound (~6.4TB/s achieved).
//
// R5: 256-bit global accesses (Blackwell LDG.E.256 / STG.E.256 via
// ld/st.global.cs.v8.f32). Halves request count; 1KB per warp per access;
// longest possible contiguous DRAM bursts. CTA still owns a contiguous
// 64KB span; W held in registers; .cs streaming policy on both streams.

static constexpr int N_ROWS  = 16384;
static constexpr int D8      = 4096 / 8;          // 512 v8-chunks per row
static constexpr int THREADS = 256;
static constexpr int R       = 8;                 // v8 accesses per thread
static constexpr long long TOTAL8 = (long long)N_ROWS * D8;   // 8,388,608
static constexpr int GRID    = (int)(TOTAL8 / (THREADS * R)); // 4096

__global__ void __launch_bounds__(THREADS) diag_scale_v8_kernel(
    const float* __restrict__ in,
    const float* __restrict__ w,
    float* __restrict__ out)
{
    // Linear v8-chunk index. Per iteration i, chunk = base + i*THREADS.
    // Chunk column within row = chunk & (D8-1). base = b*2048 + tid, and
    // 2048 % 512 == 0, so column = (tid + i*256) & 511 = tid + (i&1)*256.
    unsigned base = blockIdx.x * (THREADS * R) + threadIdx.x;

    // W for the two alternating column positions (8 floats each).
    const float4* w4 = (const float4*)w;
    float4 we0 = __ldg(&w4[threadIdx.x * 2]);            // col = tid, lo
    float4 we1 = __ldg(&w4[threadIdx.x * 2 + 1]);        //            hi
    float4 wo0 = __ldg(&w4[(threadIdx.x + 256) * 2]);    // col = tid+256
    float4 wo1 = __ldg(&w4[(threadIdx.x + 256) * 2 + 1]);

    float a[R][8];
#pragma unroll
    for (int i = 0; i < R; i++) {
        const float* p = in + (size_t)(base + i * THREADS) * 8;
        asm volatile(
            "ld.global.cs.v8.f32 {%0,%1,%2,%3,%4,%5,%6,%7}, [%8];"
            : "=f"(a[i][0]), "=f"(a[i][1]), "=f"(a[i][2]), "=f"(a[i][3]),
              "=f"(a[i][4]), "=f"(a[i][5]), "=f"(a[i][6]), "=f"(a[i][7])
            : "l"(p));
    }

#pragma unroll
    for (int i = 0; i < R; i++) {
        float4 wl = (i & 1) ? wo0 : we0;
        float4 wh = (i & 1) ? wo1 : we1;
        float r0 = a[i][0] * wl.x, r1 = a[i][1] * wl.y;
        float r2 = a[i][2] * wl.z, r3 = a[i][3] * wl.w;
        float r4 = a[i][4] * wh.x, r5 = a[i][5] * wh.y;
        float r6 = a[i][6] * wh.z, r7 = a[i][7] * wh.w;
        float* p = out + (size_t)(base + i * THREADS) * 8;
        asm volatile(
            "st.global.cs.v8.f32 [%0], {%1,%2,%3,%4,%5,%6,%7,%8};"
            :: "l"(p),
               "f"(r0), "f"(r1), "f"(r2), "f"(r3),
               "f"(r4), "f"(r5), "f"(r6), "f"(r7)
            : "memory");
    }
}

extern "C" void kernel_launch(void* const* d_in, const int* in_sizes, int n_in,
                              void* d_out, int out_size) {
    const float* in = (const float*)d_in[0];
    const float* w  = (const float*)d_in[1];
    float* out = (float*)d_out;
    diag_scale_v8_kernel<<<GRID, THREADS>>>(in, w, out);
}

// round 8
// speedup vs baseline: 1.0027x; 1.0004x over previous
#include <cuda_runtime.h>
#include <cuda_bf16.h>
#include <cstdint>

// out[n, d] = input[n, d] * W[d];  N=16384, D=4096, fp32.
// Pure stream: 256MB read + 256MB write. DRAM-bound; sustained replay
// ceiling measured at ~6.25TB/s (bench pinned at ~82us across 5 variants).
//
// R6: v8 (256-bit) accesses + higher occupancy. R=4 chunks/thread cuts
// register pressure (~55 regs) -> ~2x resident warps vs R5, while keeping
// LDG.E.256/STG.E.256 burst width and .cs streaming policy.

static constexpr int N_ROWS  = 16384;
static constexpr int D8      = 4096 / 8;            // 512 v8-chunks per row
static constexpr int THREADS = 256;
static constexpr int R       = 4;                   // v8 accesses per thread
static constexpr long long TOTAL8 = (long long)N_ROWS * D8;     // 8,388,608
static constexpr int GRID    = (int)(TOTAL8 / (THREADS * R));   // 8192

__global__ void __launch_bounds__(THREADS) diag_scale_v8r4_kernel(
    const float* __restrict__ in,
    const float* __restrict__ w,
    float* __restrict__ out)
{
    // CTA owns a contiguous 32KB span: chunks [b*1024, b*1024+1024).
    // Iteration i chunk = base + i*256; column = (tid + i*256) & 511
    //   = tid + (i&1)*256   (since base % 512 == tid).
    unsigned base = blockIdx.x * (THREADS * R) + threadIdx.x;

    const float4* w4 = (const float4*)w;
    float4 we0 = __ldg(&w4[threadIdx.x * 2]);
    float4 we1 = __ldg(&w4[threadIdx.x * 2 + 1]);
    float4 wo0 = __ldg(&w4[(threadIdx.x + 256) * 2]);
    float4 wo1 = __ldg(&w4[(threadIdx.x + 256) * 2 + 1]);

    float a[R][8];
#pragma unroll
    for (int i = 0; i < R; i++) {
        const float* p = in + (size_t)(base + i * THREADS) * 8;
        asm volatile(
            "ld.global.cs.v8.f32 {%0,%1,%2,%3,%4,%5,%6,%7}, [%8];"
            : "=f"(a[i][0]), "=f"(a[i][1]), "=f"(a[i][2]), "=f"(a[i][3]),
              "=f"(a[i][4]), "=f"(a[i][5]), "=f"(a[i][6]), "=f"(a[i][7])
            : "l"(p));
    }

#pragma unroll
    for (int i = 0; i < R; i++) {
        float4 wl = (i & 1) ? wo0 : we0;
        float4 wh = (i & 1) ? wo1 : we1;
        float r0 = a[i][0] * wl.x, r1 = a[i][1] * wl.y;
        float r2 = a[i][2] * wl.z, r3 = a[i][3] * wl.w;
        float r4 = a[i][4] * wh.x, r5 = a[i][5] * wh.y;
        float r6 = a[i][6] * wh.z, r7 = a[i][7] * wh.w;
        float* p = out + (size_t)(base + i * THREADS) * 8;
        asm volatile(
            "st.global.cs.v8.f32 [%0], {%1,%2,%3,%4,%5,%6,%7,%8};"
            :: "l"(p),
               "f"(r0), "f"(r1), "f"(r2), "f"(r3),
               "f"(r4), "f"(r5), "f"(r6), "f"(r7)
            : "memory");
    }
}

extern "C" void kernel_launch(void* const* d_in, const int* in_sizes, int n_in,
                              void* d_out, int out_size) {
    const float* in = (const float*)d_in[0];
    const float* w  = (const float*)d_in[1];
    float* out = (float*)d_out;
    diag_scale_v8r4_kernel<<<GRID, THREADS>>>(in, w, out);
}